// round 1
// baseline (speedup 1.0000x reference)
#include <cuda_runtime.h>
#include <cstdint>
#include <math.h>

// Problem dims
#define NE    16
#define NTOK  2048
#define DDIM  1024
#define HDIM  4096

// Scratch: hidden activations (E, N, H) fp32 = 512 MB, static device global (no allocs allowed)
__device__ float g_hidden[(size_t)NE * NTOK * HDIM];

// Tile config
constexpr int BM = 128, BN = 128, BK = 32;
constexpr int AS_STRIDE = BK + 4;    // 36 floats: cp.async 16B-aligned, conflict-free frag reads (4r+c)
constexpr int BS_STRIDE = BN + 8;    // 136 floats: conflict-free frag reads (8c+r)
constexpr int AS_SIZE = BM * AS_STRIDE;   // per stage
constexpr int BS_SIZE = BK * BS_STRIDE;   // per stage
constexpr int SMEM_FLOATS = 2 * (AS_SIZE + BS_SIZE);   // double buffered: 71680 B

__device__ __forceinline__ uint32_t f2tf32(float x) {
    uint32_t r;
    asm("cvt.rna.tf32.f32 %0, %1;" : "=r"(r) : "f"(x));
    return r;
}

__device__ __forceinline__ float gelu_exact(float x) {
    return 0.5f * x * (1.0f + erff(x * 0.7071067811865476f));
}

// C[M,N] = A[M,K] @ B[K,N] (+bias, optional exact GELU), all row-major fp32, TF32 tensor cores.
// Grid: (N/BN, M/BM, experts). KD is a compile-time K.
template <int KD, bool DO_GELU>
__global__ __launch_bounds__(256)
void gemm_tf32_kernel(const float* __restrict__ A,
                      const float* __restrict__ B,
                      const float* __restrict__ bias,
                      float* __restrict__ C,
                      int ldn,                  // N (ld of B and C)
                      size_t batchA, size_t batchB, size_t batchC)
{
    extern __shared__ float smem[];
    float* As = smem;                    // 2 stages of [BM][AS_STRIDE]
    float* Bs = smem + 2 * AS_SIZE;      // 2 stages of [BK][BS_STRIDE]

    const int tid  = threadIdx.x;
    const int warp = tid >> 5;
    const int lane = tid & 31;
    const int wm = warp & 3;             // 4 warps along M
    const int wn = warp >> 2;            // 2 warps along N
    const int m0 = wm * 32;              // warp tile: 32 x 64
    const int n0 = wn * 64;
    const int r  = lane >> 2;            // groupID
    const int c  = lane & 3;             // threadID_in_group

    const float* Ab = A + (size_t)blockIdx.z * batchA + (size_t)(blockIdx.y * BM) * KD;
    const float* Bb = B + (size_t)blockIdx.z * batchB + (size_t)(blockIdx.x * BN);

    auto load_tile = [&](int kt, int s) {
        // A tile: BM x BK, 16B cp.async
        #pragma unroll
        for (int i = 0; i < 4; i++) {
            int row  = (tid >> 3) + i * 32;
            int col4 = (tid & 7) * 4;
            uint32_t sa = (uint32_t)__cvta_generic_to_shared(
                &As[s * AS_SIZE + row * AS_STRIDE + col4]);
            const float* g = Ab + (size_t)row * KD + kt * BK + col4;
            asm volatile("cp.async.cg.shared.global [%0], [%1], 16;" :: "r"(sa), "l"(g));
        }
        // B tile: BK x BN
        #pragma unroll
        for (int i = 0; i < 4; i++) {
            int row  = (tid >> 5) + i * 8;
            int col4 = (tid & 31) * 4;
            uint32_t sb = (uint32_t)__cvta_generic_to_shared(
                &Bs[s * BS_SIZE + row * BS_STRIDE + col4]);
            const float* g = Bb + (size_t)(kt * BK + row) * ldn + col4;
            asm volatile("cp.async.cg.shared.global [%0], [%1], 16;" :: "r"(sb), "l"(g));
        }
        asm volatile("cp.async.commit_group;");
    };

    float acc[2][8][4];
    #pragma unroll
    for (int im = 0; im < 2; im++)
        #pragma unroll
        for (int in = 0; in < 8; in++)
            #pragma unroll
            for (int q = 0; q < 4; q++)
                acc[im][in][q] = 0.0f;

    constexpr int NT = KD / BK;
    load_tile(0, 0);

    for (int t = 0; t < NT; ++t) {
        if (t + 1 < NT) {
            load_tile(t + 1, (t + 1) & 1);
            asm volatile("cp.async.wait_group 1;");
        } else {
            asm volatile("cp.async.wait_group 0;");
        }
        __syncthreads();

        const float* as = As + (t & 1) * AS_SIZE;
        const float* bs = Bs + (t & 1) * BS_SIZE;

        #pragma unroll
        for (int kk = 0; kk < BK; kk += 8) {
            uint32_t af[2][4];
            #pragma unroll
            for (int im = 0; im < 2; im++) {
                int row = m0 + im * 16 + r;
                af[im][0] = f2tf32(as[row * AS_STRIDE + kk + c]);
                af[im][1] = f2tf32(as[(row + 8) * AS_STRIDE + kk + c]);
                af[im][2] = f2tf32(as[row * AS_STRIDE + kk + c + 4]);
                af[im][3] = f2tf32(as[(row + 8) * AS_STRIDE + kk + c + 4]);
            }
            uint32_t bf[8][2];
            #pragma unroll
            for (int in = 0; in < 8; in++) {
                int col = n0 + in * 8 + r;
                bf[in][0] = f2tf32(bs[(kk + c) * BS_STRIDE + col]);
                bf[in][1] = f2tf32(bs[(kk + c + 4) * BS_STRIDE + col]);
            }
            #pragma unroll
            for (int im = 0; im < 2; im++)
                #pragma unroll
                for (int in = 0; in < 8; in++) {
                    float* cc = acc[im][in];
                    asm volatile(
                        "mma.sync.aligned.m16n8k8.row.col.f32.tf32.tf32.f32 "
                        "{%0,%1,%2,%3},{%4,%5,%6,%7},{%8,%9},{%0,%1,%2,%3};"
                        : "+f"(cc[0]), "+f"(cc[1]), "+f"(cc[2]), "+f"(cc[3])
                        : "r"(af[im][0]), "r"(af[im][1]), "r"(af[im][2]), "r"(af[im][3]),
                          "r"(bf[in][0]), "r"(bf[in][1]));
                }
        }
        __syncthreads();
    }

    // Epilogue: bias (+GELU) and store
    float* Cb = C + (size_t)blockIdx.z * batchC;
    #pragma unroll
    for (int im = 0; im < 2; im++) {
        #pragma unroll
        for (int in = 0; in < 8; in++) {
            int grow = blockIdx.y * BM + m0 + im * 16 + r;
            int gcol = blockIdx.x * BN + n0 + in * 8 + c * 2;
            float bv0 = bias[gcol];
            float bv1 = bias[gcol + 1];
            float v0 = acc[im][in][0] + bv0;
            float v1 = acc[im][in][1] + bv1;
            float v2 = acc[im][in][2] + bv0;
            float v3 = acc[im][in][3] + bv1;
            if (DO_GELU) {
                v0 = gelu_exact(v0); v1 = gelu_exact(v1);
                v2 = gelu_exact(v2); v3 = gelu_exact(v3);
            }
            *(float2*)(Cb + (size_t)grow * ldn + gcol)       = make_float2(v0, v1);
            *(float2*)(Cb + (size_t)(grow + 8) * ldn + gcol) = make_float2(v2, v3);
        }
    }
}

extern "C" void kernel_launch(void* const* d_in, const int* in_sizes, int n_in,
                              void* d_out, int out_size)
{
    const float* x  = (const float*)d_in[0];
    const float* w1 = (const float*)d_in[1];
    const float* w2 = (const float*)d_in[2];
    const float* b1 = (const float*)d_in[3];
    const float* b2 = (const float*)d_in[4];
    float* out = (float*)d_out;

    float* hidden = nullptr;
    cudaGetSymbolAddress((void**)&hidden, g_hidden);

    size_t smem = (size_t)SMEM_FLOATS * sizeof(float);   // 71680 B
    cudaFuncSetAttribute(gemm_tf32_kernel<DDIM, true>,
                         cudaFuncAttributeMaxDynamicSharedMemorySize, (int)smem);
    cudaFuncSetAttribute(gemm_tf32_kernel<HDIM, false>,
                         cudaFuncAttributeMaxDynamicSharedMemorySize, (int)smem);

    // GEMM1: hidden = GELU(x @ w1 + b1)   per expert: (2048x1024)@(1024x4096)
    dim3 g1(HDIM / BN, NTOK / BM, NE);
    gemm_tf32_kernel<DDIM, true><<<g1, 256, smem>>>(
        x, w1, b1, hidden, HDIM,
        (size_t)NTOK * DDIM, (size_t)DDIM * HDIM, (size_t)NTOK * HDIM);

    // GEMM2: out = hidden @ w2 + b2       per expert: (2048x4096)@(4096x1024)
    dim3 g2(DDIM / BN, NTOK / BM, NE);
    gemm_tf32_kernel<HDIM, false><<<g2, 256, smem>>>(
        hidden, w2, b2, out, DDIM,
        (size_t)NTOK * HDIM, (size_t)HDIM * DDIM, (size_t)NTOK * DDIM);
}

// round 5
// speedup vs baseline: 1.0603x; 1.0603x over previous
#include <cuda_runtime.h>
#include <cstdint>
#include <math.h>

// Problem dims
#define NE    16
#define NTOK  2048
#define DDIM  1024
#define HDIM  4096

// Static scratch (no allocs allowed)
__device__ float g_hidden[(size_t)NE * NTOK * HDIM];   // GEMM1 out (tf32-rounded values)
__device__ float g_xc [(size_t)NE * NTOK * DDIM];      // x  pre-rounded to tf32
__device__ float g_w1c[(size_t)NE * DDIM * HDIM];      // w1 pre-rounded to tf32
__device__ float g_w2c[(size_t)NE * DDIM * HDIM];      // w2 pre-rounded to tf32

__device__ __forceinline__ float rnaf(float x) {
    uint32_t r; asm("cvt.rna.tf32.f32 %0, %1;" : "=r"(r) : "f"(x));
    return __uint_as_float(r);
}
__device__ __forceinline__ float gelu_exact(float x) {
    return 0.5f * x * (1.0f + erff(x * 0.7071067811865476f));
}

// ===================== GEMM config =====================
// Block tile 256(M) x 128(N) x 32(K); 8 warps, warp tile 64x64.
constexpr int BM = 256, BN = 128, BK = 32;
constexpr int AS_STRIDE = BK + 4;     // 36: conflict-free frag reads (banks 4r+c)
constexpr int BS_STRIDE = BN + 8;     // 136: conflict-free frag reads (banks 8c+r)
constexpr int AS_SIZE = BM * AS_STRIDE;    // 9216 floats / stage
constexpr int BS_SIZE = BK * BS_STRIDE;    // 4352 floats / stage
constexpr int SMEM_FLOATS = 2 * (AS_SIZE + BS_SIZE);   // 27136 floats = 108544 B

// C[M,N] = A[M,K] @ B[K,N] (+bias, optional GELU+rna). Inputs pre-rounded to tf32.
template <int KD, bool DO_GELU>
__global__ __launch_bounds__(256, 1)
void gemm_tf32_v2(const float* __restrict__ A,
                  const float* __restrict__ B,
                  const float* __restrict__ bias,
                  float* __restrict__ C,
                  int ldn,
                  size_t batchA, size_t batchB, size_t batchC)
{
    extern __shared__ float smem[];
    float* As = smem;                    // 2 stages of [BM][36]
    float* Bs = smem + 2 * AS_SIZE;      // 2 stages of [BK][136]

    const int tid  = threadIdx.x;
    const int warp = tid >> 5;
    const int lane = tid & 31;
    const int wm = warp & 3;             // 4 warps along M
    const int wn = warp >> 2;            // 2 warps along N
    const int m0 = wm * 64;              // warp tile 64 x 64
    const int n0 = wn * 64;
    const int r  = lane >> 2;
    const int c  = lane & 3;

    const float* Ab = A + (size_t)blockIdx.z * batchA + (size_t)(blockIdx.y * BM) * KD;
    const float* Bb = B + (size_t)blockIdx.z * batchB + (size_t)(blockIdx.x * BN);

    auto load_tile = [&](int kt, int s) {
        // A tile: 256 x 32, 16B cp.async (8 per thread)
        #pragma unroll
        for (int i = 0; i < 8; i++) {
            int row  = (tid >> 3) + i * 32;
            int col4 = (tid & 7) * 4;
            uint32_t sa = (uint32_t)__cvta_generic_to_shared(
                &As[s * AS_SIZE + row * AS_STRIDE + col4]);
            const float* g = Ab + (size_t)row * KD + kt * BK + col4;
            asm volatile("cp.async.cg.shared.global [%0], [%1], 16;" :: "r"(sa), "l"(g));
        }
        // B tile: 32 x 128 (4 per thread)
        #pragma unroll
        for (int i = 0; i < 4; i++) {
            int row  = (tid >> 5) + i * 8;
            int col4 = (tid & 31) * 4;
            uint32_t sb = (uint32_t)__cvta_generic_to_shared(
                &Bs[s * BS_SIZE + row * BS_STRIDE + col4]);
            const float* g = Bb + (size_t)(kt * BK + row) * ldn + col4;
            asm volatile("cp.async.cg.shared.global [%0], [%1], 16;" :: "r"(sb), "l"(g));
        }
        asm volatile("cp.async.commit_group;");
    };

    float acc[4][8][4];
    #pragma unroll
    for (int im = 0; im < 4; im++)
        #pragma unroll
        for (int in = 0; in < 8; in++)
            #pragma unroll
            for (int q = 0; q < 4; q++)
                acc[im][in][q] = 0.0f;

    constexpr int NT = KD / BK;
    load_tile(0, 0);

    for (int t = 0; t < NT; ++t) {
        if (t + 1 < NT) {
            load_tile(t + 1, (t + 1) & 1);
            asm volatile("cp.async.wait_group 1;");
        } else {
            asm volatile("cp.async.wait_group 0;");
        }
        __syncthreads();

        const uint32_t* as = (const uint32_t*)(As + (t & 1) * AS_SIZE);
        const uint32_t* bs = (const uint32_t*)(Bs + (t & 1) * BS_SIZE);

        #pragma unroll
        for (int kk = 0; kk < BK; kk += 8) {
            uint32_t af[4][4];
            #pragma unroll
            for (int im = 0; im < 4; im++) {
                int row = m0 + im * 16 + r;
                af[im][0] = as[row * AS_STRIDE + kk + c];
                af[im][1] = as[(row + 8) * AS_STRIDE + kk + c];
                af[im][2] = as[row * AS_STRIDE + kk + c + 4];
                af[im][3] = as[(row + 8) * AS_STRIDE + kk + c + 4];
            }
            uint32_t bf[8][2];
            #pragma unroll
            for (int in = 0; in < 8; in++) {
                int col = n0 + in * 8 + r;
                bf[in][0] = bs[(kk + c) * BS_STRIDE + col];
                bf[in][1] = bs[(kk + c + 4) * BS_STRIDE + col];
            }
            #pragma unroll
            for (int im = 0; im < 4; im++)
                #pragma unroll
                for (int in = 0; in < 8; in++) {
                    float* cc = acc[im][in];
                    asm volatile(
                        "mma.sync.aligned.m16n8k8.row.col.f32.tf32.tf32.f32 "
                        "{%0,%1,%2,%3},{%4,%5,%6,%7},{%8,%9},{%0,%1,%2,%3};"
                        : "+f"(cc[0]), "+f"(cc[1]), "+f"(cc[2]), "+f"(cc[3])
                        : "r"(af[im][0]), "r"(af[im][1]), "r"(af[im][2]), "r"(af[im][3]),
                          "r"(bf[in][0]), "r"(bf[in][1]));
                }
        }
        __syncthreads();
    }

    // Epilogue: bias (+GELU, rna-rounded so GEMM2's A needs no cvt)
    float* Cb = C + (size_t)blockIdx.z * batchC;
    #pragma unroll
    for (int im = 0; im < 4; im++) {
        #pragma unroll
        for (int in = 0; in < 8; in++) {
            int grow = blockIdx.y * BM + m0 + im * 16 + r;
            int gcol = blockIdx.x * BN + n0 + in * 8 + c * 2;
            float bv0 = bias[gcol];
            float bv1 = bias[gcol + 1];
            float v0 = acc[im][in][0] + bv0;
            float v1 = acc[im][in][1] + bv1;
            float v2 = acc[im][in][2] + bv0;
            float v3 = acc[im][in][3] + bv1;
            if (DO_GELU) {
                v0 = rnaf(gelu_exact(v0)); v1 = rnaf(gelu_exact(v1));
                v2 = rnaf(gelu_exact(v2)); v3 = rnaf(gelu_exact(v3));
            }
            *(float2*)(Cb + (size_t)grow * ldn + gcol)       = make_float2(v0, v1);
            *(float2*)(Cb + (size_t)(grow + 8) * ldn + gcol) = make_float2(v2, v3);
        }
    }
}

// ===================== Pre-pass: RNA-round to tf32 =====================
__global__ void convert_rna_kernel(const float* __restrict__ in, float* __restrict__ out, size_t n4) {
    size_t i = (size_t)blockIdx.x * blockDim.x + threadIdx.x;
    if (i < n4) {
        float4 v = ((const float4*)in)[i];
        v.x = rnaf(v.x); v.y = rnaf(v.y); v.z = rnaf(v.z); v.w = rnaf(v.w);
        ((float4*)out)[i] = v;
    }
}

extern "C" void kernel_launch(void* const* d_in, const int* in_sizes, int n_in,
                              void* d_out, int out_size)
{
    const float* x  = (const float*)d_in[0];
    const float* w1 = (const float*)d_in[1];
    const float* w2 = (const float*)d_in[2];
    const float* b1 = (const float*)d_in[3];
    const float* b2 = (const float*)d_in[4];
    float* out = (float*)d_out;

    float *hidden, *xc, *w1c, *w2c;
    cudaGetSymbolAddress((void**)&hidden, g_hidden);
    cudaGetSymbolAddress((void**)&xc,  g_xc);
    cudaGetSymbolAddress((void**)&w1c, g_w1c);
    cudaGetSymbolAddress((void**)&w2c, g_w2c);

    // Pre-round inputs to tf32 (removes all cvt from the GEMM mainloop)
    {
        size_t nx  = (size_t)NE * NTOK * DDIM / 4;
        size_t nw  = (size_t)NE * DDIM * HDIM / 4;
        convert_rna_kernel<<<(unsigned)((nx + 255) / 256), 256>>>(x,  xc,  nx);
        convert_rna_kernel<<<(unsigned)((nw + 255) / 256), 256>>>(w1, w1c, nw);
        convert_rna_kernel<<<(unsigned)((nw + 255) / 256), 256>>>(w2, w2c, nw);
    }

    size_t smem = (size_t)SMEM_FLOATS * sizeof(float);   // 108544 B
    cudaFuncSetAttribute(gemm_tf32_v2<DDIM, true>,
                         cudaFuncAttributeMaxDynamicSharedMemorySize, (int)smem);
    cudaFuncSetAttribute(gemm_tf32_v2<HDIM, false>,
                         cudaFuncAttributeMaxDynamicSharedMemorySize, (int)smem);

    // GEMM1: hidden = rna(GELU(x @ w1 + b1))   per expert (2048x1024)@(1024x4096)
    dim3 g1(HDIM / BN, NTOK / BM, NE);
    gemm_tf32_v2<DDIM, true><<<g1, 256, smem>>>(
        xc, w1c, b1, hidden, HDIM,
        (size_t)NTOK * DDIM, (size_t)DDIM * HDIM, (size_t)NTOK * HDIM);

    // GEMM2: out = hidden @ w2 + b2            per expert (2048x4096)@(4096x1024)
    dim3 g2(DDIM / BN, NTOK / BM, NE);
    gemm_tf32_v2<HDIM, false><<<g2, 256, smem>>>(
        hidden, w2c, b2, out, DDIM,
        (size_t)NTOK * HDIM, (size_t)HDIM * DDIM, (size_t)NTOK * DDIM);
}

// round 6
// speedup vs baseline: 1.2219x; 1.1524x over previous
#include <cuda_runtime.h>
#include <cstdint>
#include <math.h>

// Problem dims
#define NE    16
#define NTOK  2048
#define DDIM  1024
#define HDIM  4096

// Static scratch (no allocs allowed)
__device__ float g_hidden[(size_t)NE * NTOK * HDIM];   // GEMM1 out (tf32-rounded values)
__device__ float g_xc [(size_t)NE * NTOK * DDIM];      // x  pre-rounded to tf32 (row-major)
__device__ float g_w1t[(size_t)NE * DDIM * HDIM];      // w1 -> [E,H,D] (n-major), tf32-rounded
__device__ float g_w2t[(size_t)NE * DDIM * HDIM];      // w2 -> [E,D,H] (n-major), tf32-rounded

__device__ __forceinline__ float rnaf(float x) {
    uint32_t r; asm("cvt.rna.tf32.f32 %0, %1;" : "=r"(r) : "f"(x));
    return __uint_as_float(r);
}
__device__ __forceinline__ float gelu_exact(float x) {
    return 0.5f * x * (1.0f + erff(x * 0.7071067811865476f));
}

#define LDSM_X4(d0, d1, d2, d3, addr) \
    asm volatile("ldmatrix.sync.aligned.m8n8.x4.shared.b16 {%0,%1,%2,%3}, [%4];" \
        : "=r"(d0), "=r"(d1), "=r"(d2), "=r"(d3) : "r"(addr))

// ===================== GEMM config =====================
// Block tile 256(M) x 128(N) x 32(K); 8 warps, warp tile 64x64.
// Both A and B tiles stored as [rows][32 tf32 = 128B] with 16B-granule swizzle:
//   granule' = granule ^ (row % 8)   (conflict-free for cp.async stores + ldmatrix reads)
constexpr int BM = 256, BN = 128, BK = 32;
constexpr int A_BYTES = BM * 128;               // 32 KB / stage
constexpr int B_BYTES = BN * 128;               // 16 KB / stage
constexpr int STAGE_BYTES = A_BYTES + B_BYTES;  // 48 KB
constexpr int SMEM_BYTES  = 2 * STAGE_BYTES;    // 96 KB

// C[M,N] = A[M,K] @ B[N,K]^T (+bias, optional GELU+rna). A row-major, B n-major. tf32 pre-rounded.
template <int KD, bool DO_GELU>
__global__ __launch_bounds__(256, 1)
void gemm_tf32_v3(const float* __restrict__ A,
                  const float* __restrict__ B,     // [N][KD] n-major
                  const float* __restrict__ bias,
                  float* __restrict__ C,
                  int ldn,
                  size_t batchA, size_t batchB, size_t batchC)
{
    extern __shared__ char smem[];
    uint32_t sbase;
    asm("{ .reg .u64 t; cvta.to.shared.u64 t, %1; cvt.u32.u64 %0, t; }" : "=r"(sbase) : "l"(smem));

    const int tid  = threadIdx.x;
    const int warp = tid >> 5;
    const int lane = tid & 31;
    const int wm = warp & 3;             // 4 warps along M
    const int wn = warp >> 2;            // 2 warps along N
    const int m0 = wm * 64;              // warp tile 64 x 64
    const int n0 = wn * 64;
    const int r  = lane >> 2;
    const int c  = lane & 3;
    const int l8    = lane & 7;
    const int l16   = lane & 15;
    const int l8sel = (lane >> 3) & 1;
    const int lhi16 = lane >> 4;

    const float* Ab = A + (size_t)blockIdx.z * batchA + (size_t)(blockIdx.y * BM) * KD;
    const float* Bb = B + (size_t)blockIdx.z * batchB + (size_t)(blockIdx.x * BN) * KD;

    // cp.async write pattern (both tiles have 128B rows, KD-strided gmem rows)
    auto load_tile = [&](int kt, int s) {
        const uint32_t stage = sbase + s * STAGE_BYTES;
        // A: 256 rows
        #pragma unroll
        for (int i = 0; i < 8; i++) {
            int row   = (tid >> 3) + i * 32;
            int col16 = tid & 7;
            uint32_t dst = stage + row * 128 + ((col16 ^ (row & 7)) << 4);
            const float* g = Ab + (size_t)row * KD + kt * BK + col16 * 4;
            asm volatile("cp.async.cg.shared.global [%0], [%1], 16;" :: "r"(dst), "l"(g));
        }
        // B: 128 rows
        #pragma unroll
        for (int i = 0; i < 4; i++) {
            int row   = (tid >> 3) + i * 32;
            int col16 = tid & 7;
            uint32_t dst = stage + A_BYTES + row * 128 + ((col16 ^ (row & 7)) << 4);
            const float* g = Bb + (size_t)row * KD + kt * BK + col16 * 4;
            asm volatile("cp.async.cg.shared.global [%0], [%1], 16;" :: "r"(dst), "l"(g));
        }
        asm volatile("cp.async.commit_group;");
    };

    // Per-thread ldmatrix row offsets (bytes), stage-relative
    uint32_t aRow[4], bRow[4];
    #pragma unroll
    for (int im = 0; im < 4; im++) aRow[im] = (uint32_t)(m0 + im * 16 + l16) * 128;
    #pragma unroll
    for (int p = 0; p < 4; p++)  bRow[p]  = (uint32_t)(n0 + p * 16 + lhi16 * 8 + l8) * 128;

    float acc[4][8][4];
    #pragma unroll
    for (int im = 0; im < 4; im++)
        #pragma unroll
        for (int in = 0; in < 8; in++)
            #pragma unroll
            for (int q = 0; q < 4; q++)
                acc[im][in][q] = 0.0f;

    constexpr int NT = KD / BK;
    load_tile(0, 0);

    for (int t = 0; t < NT; ++t) {
        if (t + 1 < NT) {
            load_tile(t + 1, (t + 1) & 1);
            asm volatile("cp.async.wait_group 1;");
        } else {
            asm volatile("cp.async.wait_group 0;");
        }
        __syncthreads();

        const uint32_t aBase = sbase + (t & 1) * STAGE_BYTES;
        const uint32_t bBase = aBase + A_BYTES;

        #pragma unroll
        for (int kk = 0; kk < BK; kk += 8) {
            const int kk4 = kk >> 2;      // 0,2,4,6
            uint32_t af[4][4];
            #pragma unroll
            for (int im = 0; im < 4; im++) {
                uint32_t addr = aBase + aRow[im] + ((uint32_t)((kk4 + lhi16) ^ l8) << 4);
                LDSM_X4(af[im][0], af[im][1], af[im][2], af[im][3], addr);
            }
            uint32_t bf[8][2];
            #pragma unroll
            for (int p = 0; p < 4; p++) {
                uint32_t addr = bBase + bRow[p] + ((uint32_t)((kk4 + l8sel) ^ l8) << 4);
                LDSM_X4(bf[2 * p][0], bf[2 * p][1], bf[2 * p + 1][0], bf[2 * p + 1][1], addr);
            }
            #pragma unroll
            for (int im = 0; im < 4; im++)
                #pragma unroll
                for (int in = 0; in < 8; in++) {
                    float* cc = acc[im][in];
                    asm volatile(
                        "mma.sync.aligned.m16n8k8.row.col.f32.tf32.tf32.f32 "
                        "{%0,%1,%2,%3},{%4,%5,%6,%7},{%8,%9},{%0,%1,%2,%3};"
                        : "+f"(cc[0]), "+f"(cc[1]), "+f"(cc[2]), "+f"(cc[3])
                        : "r"(af[im][0]), "r"(af[im][1]), "r"(af[im][2]), "r"(af[im][3]),
                          "r"(bf[in][0]), "r"(bf[in][1]));
                }
        }
        __syncthreads();
    }

    // Epilogue: bias (+GELU, rna-rounded so GEMM2's A needs no cvt)
    float* Cb = C + (size_t)blockIdx.z * batchC;
    #pragma unroll
    for (int im = 0; im < 4; im++) {
        #pragma unroll
        for (int in = 0; in < 8; in++) {
            int grow = blockIdx.y * BM + m0 + im * 16 + r;
            int gcol = blockIdx.x * BN + n0 + in * 8 + c * 2;
            float bv0 = bias[gcol];
            float bv1 = bias[gcol + 1];
            float v0 = acc[im][in][0] + bv0;
            float v1 = acc[im][in][1] + bv1;
            float v2 = acc[im][in][2] + bv0;
            float v3 = acc[im][in][3] + bv1;
            if (DO_GELU) {
                v0 = rnaf(gelu_exact(v0)); v1 = rnaf(gelu_exact(v1));
                v2 = rnaf(gelu_exact(v2)); v3 = rnaf(gelu_exact(v3));
            }
            *(float2*)(Cb + (size_t)grow * ldn + gcol)       = make_float2(v0, v1);
            *(float2*)(Cb + (size_t)(grow + 8) * ldn + gcol) = make_float2(v2, v3);
        }
    }
}

// ===================== Pre-pass kernels =====================
__global__ void convert_rna_kernel(const float* __restrict__ in, float* __restrict__ out, size_t n4) {
    size_t i = (size_t)blockIdx.x * blockDim.x + threadIdx.x;
    if (i < n4) {
        float4 v = ((const float4*)in)[i];
        v.x = rnaf(v.x); v.y = rnaf(v.y); v.z = rnaf(v.z); v.w = rnaf(v.w);
        ((float4*)out)[i] = v;
    }
}

// out[e][cI][rI] = rna(in[e][rI][cI]); grid (C/32, R/32, E), block (32,8)
__global__ void transpose_cvt_kernel(const float* __restrict__ in, float* __restrict__ out, int R, int C) {
    __shared__ float tile[32][33];
    const int e  = blockIdx.z;
    const int r0 = blockIdx.y * 32;
    const int c0 = blockIdx.x * 32;
    const float* ine  = in  + (size_t)e * R * C;
    float*       oute = out + (size_t)e * R * C;
    const int tx = threadIdx.x, ty = threadIdx.y;
    #pragma unroll
    for (int k = 0; k < 4; k++)
        tile[ty + 8 * k][tx] = ine[(size_t)(r0 + ty + 8 * k) * C + c0 + tx];
    __syncthreads();
    #pragma unroll
    for (int k = 0; k < 4; k++)
        oute[(size_t)(c0 + ty + 8 * k) * R + r0 + tx] = rnaf(tile[tx][ty + 8 * k]);
}

extern "C" void kernel_launch(void* const* d_in, const int* in_sizes, int n_in,
                              void* d_out, int out_size)
{
    const float* x  = (const float*)d_in[0];
    const float* w1 = (const float*)d_in[1];
    const float* w2 = (const float*)d_in[2];
    const float* b1 = (const float*)d_in[3];
    const float* b2 = (const float*)d_in[4];
    float* out = (float*)d_out;

    float *hidden, *xc, *w1t, *w2t;
    cudaGetSymbolAddress((void**)&hidden, g_hidden);
    cudaGetSymbolAddress((void**)&xc,  g_xc);
    cudaGetSymbolAddress((void**)&w1t, g_w1t);
    cudaGetSymbolAddress((void**)&w2t, g_w2t);

    // Pre-pass: rna-round x; transpose+round w1 -> [E,H,D], w2 -> [E,D,H]
    {
        size_t nx = (size_t)NE * NTOK * DDIM / 4;
        convert_rna_kernel<<<(unsigned)((nx + 255) / 256), 256>>>(x, xc, nx);
        dim3 tb(32, 8);
        transpose_cvt_kernel<<<dim3(HDIM / 32, DDIM / 32, NE), tb>>>(w1, w1t, DDIM, HDIM);
        transpose_cvt_kernel<<<dim3(DDIM / 32, HDIM / 32, NE), tb>>>(w2, w2t, HDIM, DDIM);
    }

    cudaFuncSetAttribute(gemm_tf32_v3<DDIM, true>,
                         cudaFuncAttributeMaxDynamicSharedMemorySize, SMEM_BYTES);
    cudaFuncSetAttribute(gemm_tf32_v3<HDIM, false>,
                         cudaFuncAttributeMaxDynamicSharedMemorySize, SMEM_BYTES);

    // GEMM1: hidden = rna(GELU(x @ w1 + b1))   per expert (2048x1024)@(1024x4096)
    dim3 g1(HDIM / BN, NTOK / BM, NE);
    gemm_tf32_v3<DDIM, true><<<g1, 256, SMEM_BYTES>>>(
        xc, w1t, b1, hidden, HDIM,
        (size_t)NTOK * DDIM, (size_t)DDIM * HDIM, (size_t)NTOK * HDIM);

    // GEMM2: out = hidden @ w2 + b2            per expert (2048x4096)@(4096x1024)
    dim3 g2(DDIM / BN, NTOK / BM, NE);
    gemm_tf32_v3<HDIM, false><<<g2, 256, SMEM_BYTES>>>(
        hidden, w2t, b2, out, DDIM,
        (size_t)NTOK * HDIM, (size_t)HDIM * DDIM, (size_t)NTOK * DDIM);
}

// round 8
// speedup vs baseline: 1.3213x; 1.0813x over previous
#include <cuda_runtime.h>
#include <cstdint>
#include <math.h>

// Problem dims
#define NE    16
#define NTOK  2048
#define DDIM  1024
#define HDIM  4096

// Static scratch (no allocs allowed)
__device__ float g_hidden[(size_t)NE * NTOK * HDIM];   // GEMM1 out (tf32-rounded values)
__device__ float g_xc [(size_t)NE * NTOK * DDIM];      // x  pre-rounded to tf32 (row-major)
__device__ float g_w1t[(size_t)NE * DDIM * HDIM];      // w1 -> [E,H,D] (n-major), tf32-rounded
__device__ float g_w2t[(size_t)NE * DDIM * HDIM];      // w2 -> [E,D,H] (n-major), tf32-rounded

__device__ __forceinline__ float rnaf(float x) {
    uint32_t r; asm("cvt.rna.tf32.f32 %0, %1;" : "=r"(r) : "f"(x));
    return __uint_as_float(r);
}
__device__ __forceinline__ float gelu_exact(float x) {
    return 0.5f * x * (1.0f + erff(x * 0.7071067811865476f));
}

#define LDSM_X4(d0, d1, d2, d3, addr) \
    asm volatile("ldmatrix.sync.aligned.m8n8.x4.shared.b16 {%0,%1,%2,%3}, [%4];" \
        : "=r"(d0), "=r"(d1), "=r"(d2), "=r"(d3) : "r"(addr))

// ===================== GEMM config =====================
// Block tile 128(M) x 128(N) x 32(K); 8 warps, warp tile 32x64; 2 CTAs/SM.
// Tiles stored as [rows][32 tf32 = 128B] with 16B-granule swizzle:
//   granule' = granule ^ (row % 8)   (conflict-free cp.async stores + ldmatrix reads)
constexpr int BM = 128, BN = 128, BK = 32;
constexpr int A_BYTES = BM * 128;               // 16 KB / stage
constexpr int B_BYTES = BN * 128;               // 16 KB / stage
constexpr int STAGE_BYTES = A_BYTES + B_BYTES;  // 32 KB
constexpr int SMEM_BYTES  = 2 * STAGE_BYTES;    // 64 KB (x2 CTAs = 128 KB/SM)

// C[M,N] = A[M,K] @ B[N,K]^T (+bias, optional GELU+rna). A row-major, B n-major, tf32 pre-rounded.
template <int KD, bool DO_GELU>
__global__ __launch_bounds__(256, 2)
void gemm_tf32_v4(const float* __restrict__ A,
                  const float* __restrict__ B,     // [N][KD] n-major
                  const float* __restrict__ bias,
                  float* __restrict__ C,
                  int ldn,
                  size_t batchA, size_t batchB, size_t batchC)
{
    extern __shared__ char smem[];
    uint32_t sbase;
    asm("{ .reg .u64 t; cvta.to.shared.u64 t, %1; cvt.u32.u64 %0, t; }" : "=r"(sbase) : "l"(smem));

    const int tid  = threadIdx.x;
    const int warp = tid >> 5;
    const int lane = tid & 31;
    const int wm = warp & 3;             // 4 warps along M (32 rows each)
    const int wn = warp >> 2;            // 2 warps along N (64 cols each)
    const int m0 = wm * 32;
    const int n0 = wn * 64;
    const int r  = lane >> 2;
    const int c  = lane & 3;
    const int l8    = lane & 7;
    const int l16   = lane & 15;
    const int l8sel = (lane >> 3) & 1;
    const int lhi16 = lane >> 4;

    const float* Ab = A + (size_t)blockIdx.z * batchA + (size_t)(blockIdx.y * BM) * KD;
    const float* Bb = B + (size_t)blockIdx.z * batchB + (size_t)(blockIdx.x * BN) * KD;

    auto load_tile = [&](int kt, int s) {
        const uint32_t stage = sbase + s * STAGE_BYTES;
        // A: 128 rows x 128B (4 cp.async per thread)
        #pragma unroll
        for (int i = 0; i < 4; i++) {
            int row   = (tid >> 3) + i * 32;
            int col16 = tid & 7;
            uint32_t dst = stage + row * 128 + ((col16 ^ (row & 7)) << 4);
            const float* g = Ab + (size_t)row * KD + kt * BK + col16 * 4;
            asm volatile("cp.async.cg.shared.global [%0], [%1], 16;" :: "r"(dst), "l"(g));
        }
        // B: 128 rows x 128B
        #pragma unroll
        for (int i = 0; i < 4; i++) {
            int row   = (tid >> 3) + i * 32;
            int col16 = tid & 7;
            uint32_t dst = stage + A_BYTES + row * 128 + ((col16 ^ (row & 7)) << 4);
            const float* g = Bb + (size_t)row * KD + kt * BK + col16 * 4;
            asm volatile("cp.async.cg.shared.global [%0], [%1], 16;" :: "r"(dst), "l"(g));
        }
        asm volatile("cp.async.commit_group;");
    };

    // Per-thread ldmatrix row offsets (bytes), stage-relative
    uint32_t aRow[2], bRow[4];
    #pragma unroll
    for (int im = 0; im < 2; im++) aRow[im] = (uint32_t)(m0 + im * 16 + l16) * 128;
    #pragma unroll
    for (int p = 0; p < 4; p++)  bRow[p]  = (uint32_t)(n0 + p * 16 + lhi16 * 8 + l8) * 128;

    float acc[2][8][4];
    #pragma unroll
    for (int im = 0; im < 2; im++)
        #pragma unroll
        for (int in = 0; in < 8; in++)
            #pragma unroll
            for (int q = 0; q < 4; q++)
                acc[im][in][q] = 0.0f;

    constexpr int NT = KD / BK;
    load_tile(0, 0);

    for (int t = 0; t < NT; ++t) {
        if (t + 1 < NT) {
            load_tile(t + 1, (t + 1) & 1);
            asm volatile("cp.async.wait_group 1;");
        } else {
            asm volatile("cp.async.wait_group 0;");
        }
        __syncthreads();

        const uint32_t aBase = sbase + (t & 1) * STAGE_BYTES;
        const uint32_t bBase = aBase + A_BYTES;

        #pragma unroll
        for (int kk = 0; kk < BK; kk += 8) {
            const int kk4 = kk >> 2;      // 0,2,4,6
            uint32_t af[2][4];
            #pragma unroll
            for (int im = 0; im < 2; im++) {
                uint32_t addr = aBase + aRow[im] + ((uint32_t)((kk4 + lhi16) ^ l8) << 4);
                LDSM_X4(af[im][0], af[im][1], af[im][2], af[im][3], addr);
            }
            uint32_t bf[8][2];
            #pragma unroll
            for (int p = 0; p < 4; p++) {
                uint32_t addr = bBase + bRow[p] + ((uint32_t)((kk4 + l8sel) ^ l8) << 4);
                LDSM_X4(bf[2 * p][0], bf[2 * p][1], bf[2 * p + 1][0], bf[2 * p + 1][1], addr);
            }
            #pragma unroll
            for (int im = 0; im < 2; im++)
                #pragma unroll
                for (int in = 0; in < 8; in++) {
                    float* cc = acc[im][in];
                    asm volatile(
                        "mma.sync.aligned.m16n8k8.row.col.f32.tf32.tf32.f32 "
                        "{%0,%1,%2,%3},{%4,%5,%6,%7},{%8,%9},{%0,%1,%2,%3};"
                        : "+f"(cc[0]), "+f"(cc[1]), "+f"(cc[2]), "+f"(cc[3])
                        : "r"(af[im][0]), "r"(af[im][1]), "r"(af[im][2]), "r"(af[im][3]),
                          "r"(bf[in][0]), "r"(bf[in][1]));
                }
        }
        __syncthreads();
    }

    // Epilogue: bias (+GELU, rna-rounded so GEMM2's A needs no cvt)
    float* Cb = C + (size_t)blockIdx.z * batchC;
    #pragma unroll
    for (int im = 0; im < 2; im++) {
        #pragma unroll
        for (int in = 0; in < 8; in++) {
            int grow = blockIdx.y * BM + m0 + im * 16 + r;
            int gcol = blockIdx.x * BN + n0 + in * 8 + c * 2;
            float bv0 = bias[gcol];
            float bv1 = bias[gcol + 1];
            float v0 = acc[im][in][0] + bv0;
            float v1 = acc[im][in][1] + bv1;
            float v2 = acc[im][in][2] + bv0;
            float v3 = acc[im][in][3] + bv1;
            if (DO_GELU) {
                v0 = rnaf(gelu_exact(v0)); v1 = rnaf(gelu_exact(v1));
                v2 = rnaf(gelu_exact(v2)); v3 = rnaf(gelu_exact(v3));
            }
            *(float2*)(Cb + (size_t)grow * ldn + gcol)       = make_float2(v0, v1);
            *(float2*)(Cb + (size_t)(grow + 8) * ldn + gcol) = make_float2(v2, v3);
        }
    }
}

// ===================== Pre-pass kernels =====================
__global__ void convert_rna_kernel(const float* __restrict__ in, float* __restrict__ out, size_t n4) {
    size_t i = (size_t)blockIdx.x * blockDim.x + threadIdx.x;
    if (i < n4) {
        float4 v = ((const float4*)in)[i];
        v.x = rnaf(v.x); v.y = rnaf(v.y); v.z = rnaf(v.z); v.w = rnaf(v.w);
        ((float4*)out)[i] = v;
    }
}

// out[e][cI][rI] = rna(in[e][rI][cI]); grid (C/32, R/32, E), block (32,8)
__global__ void transpose_cvt_kernel(const float* __restrict__ in, float* __restrict__ out, int R, int C) {
    __shared__ float tile[32][33];
    const int e  = blockIdx.z;
    const int r0 = blockIdx.y * 32;
    const int c0 = blockIdx.x * 32;
    const float* ine  = in  + (size_t)e * R * C;
    float*       oute = out + (size_t)e * R * C;
    const int tx = threadIdx.x, ty = threadIdx.y;
    #pragma unroll
    for (int k = 0; k < 4; k++)
        tile[ty + 8 * k][tx] = ine[(size_t)(r0 + ty + 8 * k) * C + c0 + tx];
    __syncthreads();
    #pragma unroll
    for (int k = 0; k < 4; k++)
        oute[(size_t)(c0 + ty + 8 * k) * R + r0 + tx] = rnaf(tile[tx][ty + 8 * k]);
}

extern "C" void kernel_launch(void* const* d_in, const int* in_sizes, int n_in,
                              void* d_out, int out_size)
{
    const float* x  = (const float*)d_in[0];
    const float* w1 = (const float*)d_in[1];
    const float* w2 = (const float*)d_in[2];
    const float* b1 = (const float*)d_in[3];
    const float* b2 = (const float*)d_in[4];
    float* out = (float*)d_out;

    float *hidden, *xc, *w1t, *w2t;
    cudaGetSymbolAddress((void**)&hidden, g_hidden);
    cudaGetSymbolAddress((void**)&xc,  g_xc);
    cudaGetSymbolAddress((void**)&w1t, g_w1t);
    cudaGetSymbolAddress((void**)&w2t, g_w2t);

    // Pre-pass: rna-round x; transpose+round w1 -> [E,H,D], w2 -> [E,D,H]
    {
        size_t nx = (size_t)NE * NTOK * DDIM / 4;
        convert_rna_kernel<<<(unsigned)((nx + 255) / 256), 256>>>(x, xc, nx);
        dim3 tb(32, 8);
        transpose_cvt_kernel<<<dim3(HDIM / 32, DDIM / 32, NE), tb>>>(w1, w1t, DDIM, HDIM);
        transpose_cvt_kernel<<<dim3(DDIM / 32, HDIM / 32, NE), tb>>>(w2, w2t, HDIM, DDIM);
    }

    cudaFuncSetAttribute(gemm_tf32_v4<DDIM, true>,
                         cudaFuncAttributeMaxDynamicSharedMemorySize, SMEM_BYTES);
    cudaFuncSetAttribute(gemm_tf32_v4<HDIM, false>,
                         cudaFuncAttributeMaxDynamicSharedMemorySize, SMEM_BYTES);

    // GEMM1: hidden = rna(GELU(x @ w1 + b1))   per expert (2048x1024)@(1024x4096)
    dim3 g1(HDIM / BN, NTOK / BM, NE);
    gemm_tf32_v4<DDIM, true><<<g1, 256, SMEM_BYTES>>>(
        xc, w1t, b1, hidden, HDIM,
        (size_t)NTOK * DDIM, (size_t)DDIM * HDIM, (size_t)NTOK * HDIM);

    // GEMM2: out = hidden @ w2 + b2            per expert (2048x4096)@(4096x1024)
    dim3 g2(DDIM / BN, NTOK / BM, NE);
    gemm_tf32_v4<HDIM, false><<<g2, 256, SMEM_BYTES>>>(
        hidden, w2t, b2, out, DDIM,
        (size_t)NTOK * HDIM, (size_t)HDIM * DDIM, (size_t)NTOK * DDIM);
}

// round 10
// speedup vs baseline: 1.3353x; 1.0106x over previous
#include <cuda_runtime.h>
#include <cstdint>
#include <math.h>

// Problem dims
#define NE    16
#define NTOK  2048
#define DDIM  1024
#define HDIM  4096

// Static scratch (no allocs allowed)
__device__ float g_hidden[(size_t)NE * NTOK * HDIM];   // GEMM1 out (tf32-rounded values)
__device__ float g_xc [(size_t)NE * NTOK * DDIM];      // x  pre-rounded to tf32 (row-major)
__device__ float g_w1t[(size_t)NE * DDIM * HDIM];      // w1 -> [E,H,D] (n-major), tf32-rounded
__device__ float g_w2t[(size_t)NE * DDIM * HDIM];      // w2 -> [E,D,H] (n-major), tf32-rounded

__device__ __forceinline__ float rnaf(float x) {
    uint32_t r; asm("cvt.rna.tf32.f32 %0, %1;" : "=r"(r) : "f"(x));
    return __uint_as_float(r);
}
__device__ __forceinline__ float gelu_exact(float x) {
    return 0.5f * x * (1.0f + erff(x * 0.7071067811865476f));
}

#define LDSM_X4(d0, d1, d2, d3, addr) \
    asm volatile("ldmatrix.sync.aligned.m8n8.x4.shared.b16 {%0,%1,%2,%3}, [%4];" \
        : "=r"(d0), "=r"(d1), "=r"(d2), "=r"(d3) : "r"(addr))

// ===================== GEMM config =====================
// Block tile 128(M) x 128(N) x 32(K); 8 warps, warp tile 32x64; 2 CTAs/SM.
// 3-stage cp.async pipeline, 2 tiles in flight, ONE __syncthreads per tile.
// Tiles stored as [rows][32 tf32 = 128B] with 16B-granule swizzle:
//   granule' = granule ^ (row % 8)   (conflict-free cp.async stores + ldmatrix reads)
constexpr int BM = 128, BN = 128, BK = 32;
constexpr int STAGES = 3;
constexpr int A_BYTES = BM * 128;               // 16 KB / stage
constexpr int B_BYTES = BN * 128;               // 16 KB / stage
constexpr int STAGE_BYTES = A_BYTES + B_BYTES;  // 32 KB
constexpr int SMEM_BYTES  = STAGES * STAGE_BYTES; // 96 KB (x2 CTAs = 192 KB/SM)

// C[M,N] = A[M,K] @ B[N,K]^T (+bias, optional GELU+rna). A row-major, B n-major, tf32 pre-rounded.
template <int KD, bool DO_GELU>
__global__ __launch_bounds__(256, 2)
void gemm_tf32_v5(const float* __restrict__ A,
                  const float* __restrict__ B,     // [N][KD] n-major
                  const float* __restrict__ bias,
                  float* __restrict__ C,
                  int ldn,
                  size_t batchA, size_t batchB, size_t batchC)
{
    extern __shared__ char smem[];
    uint32_t sbase;
    asm("{ .reg .u64 t; cvta.to.shared.u64 t, %1; cvt.u32.u64 %0, t; }" : "=r"(sbase) : "l"(smem));

    const int tid  = threadIdx.x;
    const int warp = tid >> 5;
    const int lane = tid & 31;
    const int wm = warp & 3;             // 4 warps along M (32 rows each)
    const int wn = warp >> 2;            // 2 warps along N (64 cols each)
    const int m0 = wm * 32;
    const int n0 = wn * 64;
    const int r  = lane >> 2;
    const int c  = lane & 3;
    const int l8    = lane & 7;
    const int l16   = lane & 15;
    const int l8sel = (lane >> 3) & 1;
    const int lhi16 = lane >> 4;

    const float* Ab = A + (size_t)blockIdx.z * batchA + (size_t)(blockIdx.y * BM) * KD;
    const float* Bb = B + (size_t)blockIdx.z * batchB + (size_t)(blockIdx.x * BN) * KD;

    auto load_tile = [&](int kt, int s) {
        const uint32_t stage = sbase + s * STAGE_BYTES;
        // A: 128 rows x 128B (4 cp.async per thread)
        #pragma unroll
        for (int i = 0; i < 4; i++) {
            int row   = (tid >> 3) + i * 32;
            int col16 = tid & 7;
            uint32_t dst = stage + row * 128 + ((col16 ^ (row & 7)) << 4);
            const float* g = Ab + (size_t)row * KD + kt * BK + col16 * 4;
            asm volatile("cp.async.cg.shared.global [%0], [%1], 16;" :: "r"(dst), "l"(g));
        }
        // B: 128 rows x 128B
        #pragma unroll
        for (int i = 0; i < 4; i++) {
            int row   = (tid >> 3) + i * 32;
            int col16 = tid & 7;
            uint32_t dst = stage + A_BYTES + row * 128 + ((col16 ^ (row & 7)) << 4);
            const float* g = Bb + (size_t)row * KD + kt * BK + col16 * 4;
            asm volatile("cp.async.cg.shared.global [%0], [%1], 16;" :: "r"(dst), "l"(g));
        }
        asm volatile("cp.async.commit_group;");
    };

    // Per-thread ldmatrix offsets (bytes), stage-relative; swizzle granules hoisted.
    uint32_t aRow[2], bRow[4];
    #pragma unroll
    for (int im = 0; im < 2; im++) aRow[im] = (uint32_t)(m0 + im * 16 + l16) * 128;
    #pragma unroll
    for (int p = 0; p < 4; p++)  bRow[p]  = (uint32_t)(n0 + p * 16 + lhi16 * 8 + l8) * 128;
    uint32_t gA[4], gB[4];
    #pragma unroll
    for (int k = 0; k < 4; k++) {
        gA[k] = (uint32_t)(((2 * k + lhi16) ^ l8) << 4);
        gB[k] = (uint32_t)(((2 * k + l8sel) ^ l8) << 4);
    }

    float acc[2][8][4];
    #pragma unroll
    for (int im = 0; im < 2; im++)
        #pragma unroll
        for (int in = 0; in < 8; in++)
            #pragma unroll
            for (int q = 0; q < 4; q++)
                acc[im][in][q] = 0.0f;

    constexpr int NT = KD / BK;
    load_tile(0, 0);
    load_tile(1, 1);

    int stage_c = 0;   // stage holding tile t
    for (int t = 0; t < NT; ++t) {
        if (t + 1 < NT) {
            asm volatile("cp.async.wait_group 1;");   // 2 pending -> tile t done
        } else {
            asm volatile("cp.async.wait_group 0;");   // only tile t pending
        }
        __syncthreads();   // visibility of tile t; also guards stage (t+2)%3 overwrite below

        const uint32_t aBase = sbase + stage_c * STAGE_BYTES;
        const uint32_t bBase = aBase + A_BYTES;

        #pragma unroll
        for (int kki = 0; kki < 4; kki++) {
            uint32_t af[2][4];
            #pragma unroll
            for (int im = 0; im < 2; im++) {
                uint32_t addr = aBase + aRow[im] + gA[kki];
                LDSM_X4(af[im][0], af[im][1], af[im][2], af[im][3], addr);
            }
            uint32_t bf[8][2];
            #pragma unroll
            for (int p = 0; p < 4; p++) {
                uint32_t addr = bBase + bRow[p] + gB[kki];
                LDSM_X4(bf[2 * p][0], bf[2 * p][1], bf[2 * p + 1][0], bf[2 * p + 1][1], addr);
            }
            #pragma unroll
            for (int im = 0; im < 2; im++)
                #pragma unroll
                for (int in = 0; in < 8; in++) {
                    float* cc = acc[im][in];
                    asm volatile(
                        "mma.sync.aligned.m16n8k8.row.col.f32.tf32.tf32.f32 "
                        "{%0,%1,%2,%3},{%4,%5,%6,%7},{%8,%9},{%0,%1,%2,%3};"
                        : "+f"(cc[0]), "+f"(cc[1]), "+f"(cc[2]), "+f"(cc[3])
                        : "r"(af[im][0]), "r"(af[im][1]), "r"(af[im][2]), "r"(af[im][3]),
                          "r"(bf[in][0]), "r"(bf[in][1]));
                }
        }

        if (t + 2 < NT) {
            int s = stage_c + 2; if (s >= STAGES) s -= STAGES;   // (t+2) % 3
            load_tile(t + 2, s);
        }
        if (++stage_c == STAGES) stage_c = 0;
    }

    // Epilogue: bias (+GELU, rna-rounded so GEMM2's A needs no cvt)
    float* Cb = C + (size_t)blockIdx.z * batchC;
    #pragma unroll
    for (int im = 0; im < 2; im++) {
        #pragma unroll
        for (int in = 0; in < 8; in++) {
            int grow = blockIdx.y * BM + m0 + im * 16 + r;
            int gcol = blockIdx.x * BN + n0 + in * 8 + c * 2;
            float bv0 = bias[gcol];
            float bv1 = bias[gcol + 1];
            float v0 = acc[im][in][0] + bv0;
            float v1 = acc[im][in][1] + bv1;
            float v2 = acc[im][in][2] + bv0;
            float v3 = acc[im][in][3] + bv1;
            if (DO_GELU) {
                v0 = rnaf(gelu_exact(v0)); v1 = rnaf(gelu_exact(v1));
                v2 = rnaf(gelu_exact(v2)); v3 = rnaf(gelu_exact(v3));
            }
            *(float2*)(Cb + (size_t)grow * ldn + gcol)       = make_float2(v0, v1);
            *(float2*)(Cb + (size_t)(grow + 8) * ldn + gcol) = make_float2(v2, v3);
        }
    }
}

// ===================== Pre-pass kernels =====================
__global__ void convert_rna_kernel(const float* __restrict__ in, float* __restrict__ out, size_t n4) {
    size_t i = (size_t)blockIdx.x * blockDim.x + threadIdx.x;
    if (i < n4) {
        float4 v = ((const float4*)in)[i];
        v.x = rnaf(v.x); v.y = rnaf(v.y); v.z = rnaf(v.z); v.w = rnaf(v.w);
        ((float4*)out)[i] = v;
    }
}

// out[e][cI][rI] = rna(in[e][rI][cI]); grid (C/32, R/32, E), block (32,8)
__global__ void transpose_cvt_kernel(const float* __restrict__ in, float* __restrict__ out, int R, int C) {
    __shared__ float tile[32][33];
    const int e  = blockIdx.z;
    const int r0 = blockIdx.y * 32;
    const int c0 = blockIdx.x * 32;
    const float* ine  = in  + (size_t)e * R * C;
    float*       oute = out + (size_t)e * R * C;
    const int tx = threadIdx.x, ty = threadIdx.y;
    #pragma unroll
    for (int k = 0; k < 4; k++)
        tile[ty + 8 * k][tx] = ine[(size_t)(r0 + ty + 8 * k) * C + c0 + tx];
    __syncthreads();
    #pragma unroll
    for (int k = 0; k < 4; k++)
        oute[(size_t)(c0 + ty + 8 * k) * R + r0 + tx] = rnaf(tile[tx][ty + 8 * k]);
}

extern "C" void kernel_launch(void* const* d_in, const int* in_sizes, int n_in,
                              void* d_out, int out_size)
{
    const float* x  = (const float*)d_in[0];
    const float* w1 = (const float*)d_in[1];
    const float* w2 = (const float*)d_in[2];
    const float* b1 = (const float*)d_in[3];
    const float* b2 = (const float*)d_in[4];
    float* out = (float*)d_out;

    float *hidden, *xc, *w1t, *w2t;
    cudaGetSymbolAddress((void**)&hidden, g_hidden);
    cudaGetSymbolAddress((void**)&xc,  g_xc);
    cudaGetSymbolAddress((void**)&w1t, g_w1t);
    cudaGetSymbolAddress((void**)&w2t, g_w2t);

    // Pre-pass: rna-round x; transpose+round w1 -> [E,H,D], w2 -> [E,D,H]
    {
        size_t nx = (size_t)NE * NTOK * DDIM / 4;
        convert_rna_kernel<<<(unsigned)((nx + 255) / 256), 256>>>(x, xc, nx);
        dim3 tb(32, 8);
        transpose_cvt_kernel<<<dim3(HDIM / 32, DDIM / 32, NE), tb>>>(w1, w1t, DDIM, HDIM);
        transpose_cvt_kernel<<<dim3(DDIM / 32, HDIM / 32, NE), tb>>>(w2, w2t, HDIM, DDIM);
    }

    cudaFuncSetAttribute(gemm_tf32_v5<DDIM, true>,
                         cudaFuncAttributeMaxDynamicSharedMemorySize, SMEM_BYTES);
    cudaFuncSetAttribute(gemm_tf32_v5<HDIM, false>,
                         cudaFuncAttributeMaxDynamicSharedMemorySize, SMEM_BYTES);

    // GEMM1: hidden = rna(GELU(x @ w1 + b1))   per expert (2048x1024)@(1024x4096)
    dim3 g1(HDIM / BN, NTOK / BM, NE);
    gemm_tf32_v5<DDIM, true><<<g1, 256, SMEM_BYTES>>>(
        xc, w1t, b1, hidden, HDIM,
        (size_t)NTOK * DDIM, (size_t)DDIM * HDIM, (size_t)NTOK * HDIM);

    // GEMM2: out = hidden @ w2 + b2            per expert (2048x4096)@(4096x1024)
    dim3 g2(DDIM / BN, NTOK / BM, NE);
    gemm_tf32_v5<HDIM, false><<<g2, 256, SMEM_BYTES>>>(
        hidden, w2t, b2, out, DDIM,
        (size_t)NTOK * HDIM, (size_t)HDIM * DDIM, (size_t)NTOK * DDIM);
}